// round 2
// baseline (speedup 1.0000x reference)
#include <cuda_runtime.h>
#include <cuda_bf16.h>

#define DD 256
#define NTHREADS 256
#define BN_EPS 1e-3f

__global__ __launch_bounds__(NTHREADS)
void hypernet_residual_kernel(
    const float* __restrict__ xin,
    const float* __restrict__ w1,
    const float* __restrict__ b1,
    const float* __restrict__ w2,
    const float* __restrict__ b2,
    const float* __restrict__ g1, const float* __restrict__ be1,
    const float* __restrict__ m1, const float* __restrict__ v1,
    const float* __restrict__ g2, const float* __restrict__ be2,
    const float* __restrict__ m2, const float* __restrict__ v2,
    float* __restrict__ out)
{
    const int b = blockIdx.x;
    const int t = threadIdx.x;
    const int g = t & 63;    // e-group: covers e = 4g .. 4g+3
    const int r = t >> 6;    // row-phase: d = r, r+4, r+8, ...

    __shared__ float  xs[DD];      // activated vector feeding the matvec
    __shared__ float  xin_s[DD];   // raw input row for residual
    __shared__ float4 red[NTHREADS];

    // ---------------- Phase A: BN1 + ReLU ----------------
    {
        float xv = xin[(size_t)b * DD + t];
        xin_s[t] = xv;
        float h = g1[t] * (xv - m1[t]) * rsqrtf(v1[t] + BN_EPS) + be1[t];
        xs[t] = fmaxf(h, 0.0f);
    }

    // Prefetch epilogue-1 operands on the reducing threads so their global
    // latency overlaps the matvec-1 weight stream.
    float4 p_b1, p_g2, p_m2, p_v2, p_be2;
    if (r == 0) {
        p_b1  = reinterpret_cast<const float4*>(b1 + (size_t)b * DD)[g];
        p_g2  = reinterpret_cast<const float4*>(g2)[g];
        p_m2  = reinterpret_cast<const float4*>(m2)[g];
        p_v2  = reinterpret_cast<const float4*>(v2)[g];
        p_be2 = reinterpret_cast<const float4*>(be2)[g];
    }
    __syncthreads();

    // ---------------- Matvec 1: y1[e] = sum_d xs[d] * W1[b,d,e] ----------------
    const float4* W1 = reinterpret_cast<const float4*>(w1 + (size_t)b * DD * DD);
    float4 acc = make_float4(0.f, 0.f, 0.f, 0.f);
    #pragma unroll 8
    for (int d = r; d < DD; d += 4) {
        float4 wv = __ldcs(&W1[d * 64 + g]);
        float  x  = xs[d];
        acc.x = fmaf(x, wv.x, acc.x);
        acc.y = fmaf(x, wv.y, acc.y);
        acc.z = fmaf(x, wv.z, acc.z);
        acc.w = fmaf(x, wv.w, acc.w);
    }
    red[t] = acc;
    __syncthreads();   // also guarantees all reads of xs[] are done

    // ---------------- Reduce, +b1, BN2 + ReLU -> xs ----------------
    if (r == 0) {
        float4 a0 = red[g];
        float4 a1 = red[g + 64];
        float4 a2 = red[g + 128];
        float4 a3 = red[g + 192];

        float y0 = a0.x + a1.x + a2.x + a3.x + p_b1.x;
        float y1 = a0.y + a1.y + a2.y + a3.y + p_b1.y;
        float y2 = a0.z + a1.z + a2.z + a3.z + p_b1.z;
        float y3 = a0.w + a1.w + a2.w + a3.w + p_b1.w;

        int e = 4 * g;
        xs[e + 0] = fmaxf(p_g2.x * (y0 - p_m2.x) * rsqrtf(p_v2.x + BN_EPS) + p_be2.x, 0.0f);
        xs[e + 1] = fmaxf(p_g2.y * (y1 - p_m2.y) * rsqrtf(p_v2.y + BN_EPS) + p_be2.y, 0.0f);
        xs[e + 2] = fmaxf(p_g2.z * (y2 - p_m2.z) * rsqrtf(p_v2.z + BN_EPS) + p_be2.z, 0.0f);
        xs[e + 3] = fmaxf(p_g2.w * (y3 - p_m2.w) * rsqrtf(p_v2.w + BN_EPS) + p_be2.w, 0.0f);
    }

    // Prefetch epilogue-2 operands (b2 row) to overlap matvec-2 stream.
    float4 p_b2;
    if (r == 0) {
        p_b2 = reinterpret_cast<const float4*>(b2 + (size_t)b * DD)[g];
    }
    __syncthreads();

    // ---------------- Matvec 2: y2[e] = sum_d xs[d] * W2[b,d,e] ----------------
    const float4* W2 = reinterpret_cast<const float4*>(w2 + (size_t)b * DD * DD);
    acc = make_float4(0.f, 0.f, 0.f, 0.f);
    #pragma unroll 8
    for (int d = r; d < DD; d += 4) {
        float4 wv = __ldcs(&W2[d * 64 + g]);
        float  x  = xs[d];
        acc.x = fmaf(x, wv.x, acc.x);
        acc.y = fmaf(x, wv.y, acc.y);
        acc.z = fmaf(x, wv.z, acc.z);
        acc.w = fmaf(x, wv.w, acc.w);
    }
    red[t] = acc;
    __syncthreads();

    // ---------------- Reduce, +b2, + residual, store ----------------
    if (r == 0) {
        float4 a0 = red[g];
        float4 a1 = red[g + 64];
        float4 a2 = red[g + 128];
        float4 a3 = red[g + 192];

        int e = 4 * g;
        float4 o;
        o.x = xin_s[e + 0] + a0.x + a1.x + a2.x + a3.x + p_b2.x;
        o.y = xin_s[e + 1] + a0.y + a1.y + a2.y + a3.y + p_b2.y;
        o.z = xin_s[e + 2] + a0.z + a1.z + a2.z + a3.z + p_b2.z;
        o.w = xin_s[e + 3] + a0.w + a1.w + a2.w + a3.w + p_b2.w;
        reinterpret_cast<float4*>(out + (size_t)b * DD)[g] = o;
    }
}

extern "C" void kernel_launch(void* const* d_in, const int* in_sizes, int n_in,
                              void* d_out, int out_size) {
    const float* xin = (const float*)d_in[0];
    const float* w1  = (const float*)d_in[1];
    const float* b1  = (const float*)d_in[2];
    const float* w2  = (const float*)d_in[3];
    const float* b2  = (const float*)d_in[4];
    const float* g1  = (const float*)d_in[5];
    const float* be1 = (const float*)d_in[6];
    const float* m1  = (const float*)d_in[7];
    const float* v1  = (const float*)d_in[8];
    const float* g2  = (const float*)d_in[9];
    const float* be2 = (const float*)d_in[10];
    const float* m2  = (const float*)d_in[11];
    const float* v2  = (const float*)d_in[12];
    float* out = (float*)d_out;

    const int batch = in_sizes[0] / DD;   // 2048
    hypernet_residual_kernel<<<batch, NTHREADS>>>(
        xin, w1, b1, w2, b2, g1, be1, m1, v1, g2, be2, m2, v2, out);
}

// round 4
// speedup vs baseline: 1.0892x; 1.0892x over previous
#include <cuda_runtime.h>
#include <cuda_bf16.h>

#define DD 256
#define NTHREADS 256
#define BN_EPS 1e-3f

__global__ __launch_bounds__(NTHREADS, 6)
void hypernet_residual_kernel(
    const float* __restrict__ xin,
    const float* __restrict__ w1,
    const float* __restrict__ b1,
    const float* __restrict__ w2,
    const float* __restrict__ b2,
    const float* __restrict__ g1, const float* __restrict__ be1,
    const float* __restrict__ m1, const float* __restrict__ v1,
    const float* __restrict__ g2, const float* __restrict__ be2,
    const float* __restrict__ m2, const float* __restrict__ v2,
    float* __restrict__ out)
{
    const int b = blockIdx.x;
    const int t = threadIdx.x;
    const int g = t & 63;    // e-group: covers e = 4g .. 4g+3
    const int r = t >> 6;    // row-phase: d = r, r+4, r+8, ...

    __shared__ float  xs[DD];      // activated vector feeding the matvec
    __shared__ float  xin_s[DD];   // raw input row for residual
    __shared__ float4 red[NTHREADS];

    // ---------------- Phase A: BN1 + ReLU ----------------
    {
        float xv = xin[(size_t)b * DD + t];
        xin_s[t] = xv;
        float h = g1[t] * (xv - m1[t]) * rsqrtf(v1[t] + BN_EPS) + be1[t];
        xs[t] = fmaxf(h, 0.0f);
    }

    // Prefetch epilogue-1 operands on the reducing threads so their global
    // latency overlaps the matvec-1 weight stream.
    float4 p_b1, p_g2, p_m2, p_v2, p_be2;
    if (r == 0) {
        p_b1  = reinterpret_cast<const float4*>(b1 + (size_t)b * DD)[g];
        p_g2  = reinterpret_cast<const float4*>(g2)[g];
        p_m2  = reinterpret_cast<const float4*>(m2)[g];
        p_v2  = reinterpret_cast<const float4*>(v2)[g];
        p_be2 = reinterpret_cast<const float4*>(be2)[g];
    }
    __syncthreads();

    // ---------------- Matvec 1: y1[e] = sum_d xs[d] * W1[b,d,e] ----------------
    const float4* W1 = reinterpret_cast<const float4*>(w1 + (size_t)b * DD * DD);
    float4 acc = make_float4(0.f, 0.f, 0.f, 0.f);
    #pragma unroll 4
    for (int d = r; d < DD; d += 4) {
        float4 wv = __ldcs(&W1[d * 64 + g]);
        float  x  = xs[d];
        acc.x = fmaf(x, wv.x, acc.x);
        acc.y = fmaf(x, wv.y, acc.y);
        acc.z = fmaf(x, wv.z, acc.z);
        acc.w = fmaf(x, wv.w, acc.w);
    }
    red[t] = acc;
    __syncthreads();   // also guarantees all reads of xs[] are done

    // ---------------- Reduce, +b1, BN2 + ReLU -> xs ----------------
    if (r == 0) {
        float4 a0 = red[g];
        float4 a1 = red[g + 64];
        float4 a2 = red[g + 128];
        float4 a3 = red[g + 192];

        float y0 = a0.x + a1.x + a2.x + a3.x + p_b1.x;
        float y1 = a0.y + a1.y + a2.y + a3.y + p_b1.y;
        float y2 = a0.z + a1.z + a2.z + a3.z + p_b1.z;
        float y3 = a0.w + a1.w + a2.w + a3.w + p_b1.w;

        int e = 4 * g;
        xs[e + 0] = fmaxf(p_g2.x * (y0 - p_m2.x) * rsqrtf(p_v2.x + BN_EPS) + p_be2.x, 0.0f);
        xs[e + 1] = fmaxf(p_g2.y * (y1 - p_m2.y) * rsqrtf(p_v2.y + BN_EPS) + p_be2.y, 0.0f);
        xs[e + 2] = fmaxf(p_g2.z * (y2 - p_m2.z) * rsqrtf(p_v2.z + BN_EPS) + p_be2.z, 0.0f);
        xs[e + 3] = fmaxf(p_g2.w * (y3 - p_m2.w) * rsqrtf(p_v2.w + BN_EPS) + p_be2.w, 0.0f);
    }

    // Prefetch epilogue-2 operands (b2 row) to overlap matvec-2 stream.
    float4 p_b2;
    if (r == 0) {
        p_b2 = reinterpret_cast<const float4*>(b2 + (size_t)b * DD)[g];
    }
    __syncthreads();

    // ---------------- Matvec 2: y2[e] = sum_d xs[d] * W2[b,d,e] ----------------
    const float4* W2 = reinterpret_cast<const float4*>(w2 + (size_t)b * DD * DD);
    acc = make_float4(0.f, 0.f, 0.f, 0.f);
    #pragma unroll 4
    for (int d = r; d < DD; d += 4) {
        float4 wv = __ldcs(&W2[d * 64 + g]);
        float  x  = xs[d];
        acc.x = fmaf(x, wv.x, acc.x);
        acc.y = fmaf(x, wv.y, acc.y);
        acc.z = fmaf(x, wv.z, acc.z);
        acc.w = fmaf(x, wv.w, acc.w);
    }
    red[t] = acc;
    __syncthreads();

    // ---------------- Reduce, +b2, + residual, store ----------------
    if (r == 0) {
        float4 a0 = red[g];
        float4 a1 = red[g + 64];
        float4 a2 = red[g + 128];
        float4 a3 = red[g + 192];

        int e = 4 * g;
        float4 o;
        o.x = xin_s[e + 0] + a0.x + a1.x + a2.x + a3.x + p_b2.x;
        o.y = xin_s[e + 1] + a0.y + a1.y + a2.y + a3.y + p_b2.y;
        o.z = xin_s[e + 2] + a0.z + a1.z + a2.z + a3.z + p_b2.z;
        o.w = xin_s[e + 3] + a0.w + a1.w + a2.w + a3.w + p_b2.w;
        reinterpret_cast<float4*>(out + (size_t)b * DD)[g] = o;
    }
}

extern "C" void kernel_launch(void* const* d_in, const int* in_sizes, int n_in,
                              void* d_out, int out_size) {
    const float* xin = (const float*)d_in[0];
    const float* w1  = (const float*)d_in[1];
    const float* b1  = (const float*)d_in[2];
    const float* w2  = (const float*)d_in[3];
    const float* b2  = (const float*)d_in[4];
    const float* g1  = (const float*)d_in[5];
    const float* be1 = (const float*)d_in[6];
    const float* m1  = (const float*)d_in[7];
    const float* v1  = (const float*)d_in[8];
    const float* g2  = (const float*)d_in[9];
    const float* be2 = (const float*)d_in[10];
    const float* m2  = (const float*)d_in[11];
    const float* v2  = (const float*)d_in[12];
    float* out = (float*)d_out;

    const int batch = in_sizes[0] / DD;   // 2048
    hypernet_residual_kernel<<<batch, NTHREADS>>>(
        xin, w1, b1, w2, b2, g1, be1, m1, v1, g2, be2, m2, v2, out);
}